// round 7
// baseline (speedup 1.0000x reference)
#include <cuda_runtime.h>
#include <cstdint>

#define NA  16
#define NR  32
#define TPB 128      // 4 warps
#define SPW 32       // samples per warp (16 f32x2 pairs)
#define PP  16       // pairs per warp
#define SPB 128      // samples per block
#define PSTRIDE 17   // u64 stride per pair in packed X (34 floats, bank-skew pad)

static __device__ __forceinline__ unsigned long long pack2(float lo, float hi) {
    unsigned long long r;
    asm("mov.b64 %0, {%1, %2};" : "=l"(r) : "f"(lo), "f"(hi));
    return r;
}
static __device__ __forceinline__ void unpack2(unsigned long long v, float& lo, float& hi) {
    asm("mov.b64 {%0, %1}, %2;" : "=f"(lo), "=f"(hi) : "l"(v));
}
static __device__ __forceinline__ unsigned long long fma2(
    unsigned long long a, unsigned long long b, unsigned long long c) {
    unsigned long long d;
    asm("fma.rn.f32x2 %0, %1, %2, %3;" : "=l"(d) : "l"(a), "l"(b), "l"(c));
    return d;
}
static __device__ __forceinline__ unsigned long long add2(
    unsigned long long a, unsigned long long b) {
    unsigned long long d;
    asm("add.rn.f32x2 %0, %1, %2;" : "=l"(d) : "l"(a), "l"(b));
    return d;
}
static __device__ __forceinline__ unsigned long long mul2(
    unsigned long long a, unsigned long long b) {
    unsigned long long d;
    asm("mul.rn.f32x2 %0, %1, %2;" : "=l"(d) : "l"(a), "l"(b));
    return d;
}
static __device__ __forceinline__ float ex2(float x) {
    float y;
    asm("ex2.approx.f32 %0, %1;" : "=f"(y) : "f"(x));
    return y;
}

__global__ void __launch_bounds__(TPB, 4)
tsk_kernel(const float* __restrict__ input,
           const float* __restrict__ frbw,
           const float* __restrict__ C,
           float* __restrict__ out, int B)
{
    // Pair-packed X per warp: packed[p][k][par] = x[2p+par][k], pair stride 34
    // floats (17 u64) so the staging STS.32 scatter is bank-conflict-free and
    // the hot-loop LDS.64 broadcast directly yields the (x_even, x_odd) f32x2.
    __shared__ unsigned long long sx[4][PP * PSTRIDE];

    const float L2E = 1.4426950408889634f;
    const int tid  = threadIdx.x;
    const int w    = tid >> 5;
    const int lane = tid & 31;
    const int ws0  = (blockIdx.x * 4 + w) * SPW;   // first sample of this warp

    // ---- stage this warp's 32 rows, pre-packed (lane l -> row l) ----
    {
        int srow = ws0 + lane;
        if (srow >= B) srow = B - 1;               // clamp tail: duplicates OK
        const float4* gsrc = (const float4*)(input + (size_t)srow * NA);
        float4 v0 = gsrc[0], v1 = gsrc[1], v2 = gsrc[2], v3 = gsrc[3];
        float xv[NA] = {v0.x, v0.y, v0.z, v0.w, v1.x, v1.y, v1.z, v1.w,
                        v2.x, v2.y, v2.z, v2.w, v3.x, v3.y, v3.z, v3.w};
        float* dst = (float*)&sx[w][(lane >> 1) * PSTRIDE];  // pair = lane/2
        const int par = lane & 1;
        #pragma unroll
        for (int k = 0; k < NA; k++) dst[k * 2 + par] = xv[k];
    }

    // ---- per-lane rule coefficients (lane = rule), register-resident ----
    // Faithful to reference: idx = r*A + k; (sigma, center) = FRB_W[idx], FRB_W[idx+1]
    unsigned long long P[NA], Q[NA], Cc[NA];
    float rc = 0.0f;
    const float* wr = frbw + lane * NA;
    const float* cr = C + lane * (NA + 1);
    #pragma unroll
    for (int k = 0; k < NA; k++) {
        float sig = __ldg(wr + k);
        float cen = __ldg(wr + k + 1);
        float is2 = 1.0f / (sig * sig);
        float p = -0.5f * is2 * L2E;
        float q = is2 * cen * L2E;
        P[k]  = pack2(p, p);
        Q[k]  = pack2(q, q);
        float c = __ldg(cr + k + 1);
        Cc[k] = pack2(c, c);
        rc += p * cen * cen;      // -0.5*(cen/sig)^2 * log2e
    }
    unsigned long long RC = pack2(rc, rc);
    float c0 = __ldg(cr);
    unsigned long long C0 = pack2(c0, c0);

    __syncwarp();   // staging visible warp-wide (warp-private smem region)

    const unsigned long long* xw = sx[w];

    // ---- main: 16 sample-pairs; hot loop = FFMA2 + broadcast LDS.64 only ----
    #pragma unroll 1
    for (int p = 0; p < PP; p++) {
        const unsigned long long* xp = xw + p * PSTRIDE;
        unsigned long long e  = RC;
        unsigned long long ch = C0;
        #pragma unroll
        for (int k = 0; k < NA; k++) {
            unsigned long long X = xp[k];          // LDS.64 broadcast = f32x2
            unsigned long long t = fma2(P[k], X, Q[k]);
            e  = fma2(t, X, e);
            ch = fma2(Cc[k], X, ch);
        }

        float e0, e1;
        unpack2(e, e0, e1);
        unsigned long long u  = pack2(ex2(e0), ex2(e1));  // firing strengths
        unsigned long long nm = mul2(u, ch);

        // sum over 32 rules = butterfly over lanes (packed f32x2 adds)
        #pragma unroll
        for (int m = 16; m >= 1; m >>= 1) {
            nm = add2(nm, __shfl_xor_sync(0xFFFFFFFFu, nm, m));
            u  = add2(u,  __shfl_xor_sync(0xFFFFFFFFu, u,  m));
        }

        if (lane == 0) {
            float n0, n1, d0, d1;
            unpack2(nm, n0, n1);
            unpack2(u,  d0, d1);
            int s = ws0 + p * 2;
            if (s + 1 < B) {
                *(float2*)(out + s) = make_float2(__fdividef(n0, d0),
                                                  __fdividef(n1, d1));
            } else if (s < B) {
                out[s] = __fdividef(n0, d0);
            }
        }
    }
}

extern "C" void kernel_launch(void* const* d_in, const int* in_sizes, int n_in,
                              void* d_out, int out_size)
{
    const float* input = (const float*)d_in[0];   // [B, 16] fp32
    const float* frbw  = (const float*)d_in[1];   // [1024]  fp32
    const float* Cm    = (const float*)d_in[2];   // [32,17] fp32
    float* out = (float*)d_out;                   // [B]     fp32

    int B = in_sizes[0] / NA;
    int blocks = (B + SPB - 1) / SPB;             // 512 blocks for B=65536
    tsk_kernel<<<blocks, TPB>>>(input, frbw, Cm, out, B);
}

// round 8
// speedup vs baseline: 1.1047x; 1.1047x over previous
#include <cuda_runtime.h>
#include <cstdint>

#define NA  16
#define NR  32
#define TPB 128      // 4 warps; warp handles 32 samples, lane = rule
#define SPW 32       // samples per warp
#define PP  16       // sample pairs per warp
#define SPB 128      // samples per block
#define XSTRIDE 18   // u64 stride per pair in packed X (16B-aligned pair base)
#define RSTRIDE 17   // u64 stride per rule row in transpose buffer

static __device__ __forceinline__ unsigned long long pack2(float lo, float hi) {
    unsigned long long r;
    asm("mov.b64 %0, {%1, %2};" : "=l"(r) : "f"(lo), "f"(hi));
    return r;
}
static __device__ __forceinline__ void unpack2(unsigned long long v, float& lo, float& hi) {
    asm("mov.b64 {%0, %1}, %2;" : "=f"(lo), "=f"(hi) : "l"(v));
}
static __device__ __forceinline__ unsigned long long fma2(
    unsigned long long a, unsigned long long b, unsigned long long c) {
    unsigned long long d;
    asm("fma.rn.f32x2 %0, %1, %2, %3;" : "=l"(d) : "l"(a), "l"(b), "l"(c));
    return d;
}
static __device__ __forceinline__ unsigned long long mul2(
    unsigned long long a, unsigned long long b) {
    unsigned long long d;
    asm("mul.rn.f32x2 %0, %1, %2;" : "=l"(d) : "l"(a), "l"(b));
    return d;
}
static __device__ __forceinline__ float ex2(float x) {
    float y;
    asm("ex2.approx.f32 %0, %1;" : "=f"(y) : "f"(x));
    return y;
}

__global__ void __launch_bounds__(TPB, 3)
tsk_kernel(const float* __restrict__ input,
           const float* __restrict__ frbw,
           const float* __restrict__ C,
           float* __restrict__ out, int B)
{
    // Pair-packed X per warp: float view [pair][k][parity], pair stride 18 u64.
    __shared__ unsigned long long sx[4][PP * XSTRIDE];          // 9.2 KB
    // Transpose reduction buffer: [warp][var][rule][pair(+pad)] u64.
    __shared__ unsigned long long red[4][2][NR][RSTRIDE];       // 34.8 KB

    const float L2E = 1.4426950408889634f;
    const int tid  = threadIdx.x;
    const int w    = tid >> 5;
    const int lane = tid & 31;
    const int ws0  = (blockIdx.x * 4 + w) * SPW;   // first sample of this warp

    // ---- stage this warp's 32 rows, pair-packed (lane l -> row l) ----
    {
        int srow = ws0 + lane;
        if (srow >= B) srow = B - 1;               // clamp tail: duplicates OK
        const float4* gsrc = (const float4*)(input + (size_t)srow * NA);
        float4 v0 = gsrc[0], v1 = gsrc[1], v2 = gsrc[2], v3 = gsrc[3];
        float xv[NA] = {v0.x, v0.y, v0.z, v0.w, v1.x, v1.y, v1.z, v1.w,
                        v2.x, v2.y, v2.z, v2.w, v3.x, v3.y, v3.z, v3.w};
        float* dst = (float*)&sx[w][(lane >> 1) * XSTRIDE];
        const int par = lane & 1;
        #pragma unroll
        for (int k = 0; k < NA; k++) dst[k * 2 + par] = xv[k];
    }

    // ---- per-lane rule coefficients (lane = rule), register-resident ----
    // Faithful to reference: idx = r*A + k; (sigma, center) = FRB_W[idx], FRB_W[idx+1]
    unsigned long long P[NA], Q[NA], Cc[NA];
    float rc = 0.0f;
    const float* wr = frbw + lane * NA;
    const float* cr = C + lane * (NA + 1);
    #pragma unroll
    for (int k = 0; k < NA; k++) {
        float sig = __ldg(wr + k);
        float cen = __ldg(wr + k + 1);
        float is2 = 1.0f / (sig * sig);
        float p = -0.5f * is2 * L2E;
        float q = is2 * cen * L2E;
        P[k]  = pack2(p, p);
        Q[k]  = pack2(q, q);
        float c = __ldg(cr + k + 1);
        Cc[k] = pack2(c, c);
        rc += p * cen * cen;      // -0.5*(cen/sig)^2 * log2e
    }
    unsigned long long RC = pack2(rc, rc);
    float c0 = __ldg(cr);
    unsigned long long C0 = pack2(c0, c0);

    __syncwarp();   // staging visible warp-wide (warp-private smem region)

    const unsigned long long* xw = sx[w];

    // ---- main: 16 pairs; hot loop = FFMA2 + 8 broadcast LDS.128 + 2 STS.64 ----
    #pragma unroll 1
    for (int p = 0; p < PP; p++) {
        const ulonglong2* xp = (const ulonglong2*)(xw + p * XSTRIDE);
        unsigned long long e  = RC;
        unsigned long long ch = C0;
        #pragma unroll
        for (int kk = 0; kk < 8; kk++) {
            ulonglong2 X2 = xp[kk];                // (X[2kk] | X[2kk+1]) broadcast
            unsigned long long t0 = fma2(P[2 * kk],     X2.x, Q[2 * kk]);
            unsigned long long t1 = fma2(P[2 * kk + 1], X2.y, Q[2 * kk + 1]);
            e  = fma2(t0, X2.x, e);
            ch = fma2(Cc[2 * kk],     X2.x, ch);
            e  = fma2(t1, X2.y, e);
            ch = fma2(Cc[2 * kk + 1], X2.y, ch);
        }

        float e0, e1;
        unpack2(e, e0, e1);
        unsigned long long u = pack2(ex2(e0), ex2(e1));  // firing strengths
        // fire-and-forget partials into the transpose buffer (no chain)
        red[w][0][lane][p] = mul2(u, ch);   // numerator partials (2 samples)
        red[w][1][lane][p] = u;             // denominator partials
    }

    __syncwarp();

    // ---- batched reduction: lane = sample, sum over 32 rules ----
    {
        const float* nmf = (const float*)&red[w][0][0][0];  // row stride 34 floats
        const float* uf  = (const float*)&red[w][1][0][0];
        // sample s=lane lives at float offset r*34 + lane (pair=lane>>1, par=lane&1)
        float n0 = 0.f, n1 = 0.f, n2 = 0.f, n3 = 0.f;
        float d0 = 0.f, d1 = 0.f, d2 = 0.f, d3 = 0.f;
        #pragma unroll
        for (int r = 0; r < NR; r += 4) {
            n0 += nmf[(r + 0) * 34 + lane];
            n1 += nmf[(r + 1) * 34 + lane];
            n2 += nmf[(r + 2) * 34 + lane];
            n3 += nmf[(r + 3) * 34 + lane];
            d0 += uf[(r + 0) * 34 + lane];
            d1 += uf[(r + 1) * 34 + lane];
            d2 += uf[(r + 2) * 34 + lane];
            d3 += uf[(r + 3) * 34 + lane];
        }
        float num = (n0 + n1) + (n2 + n3);
        float den = (d0 + d1) + (d2 + d3);
        int s = ws0 + lane;
        if (s < B) out[s] = __fdividef(num, den);
    }
}

extern "C" void kernel_launch(void* const* d_in, const int* in_sizes, int n_in,
                              void* d_out, int out_size)
{
    const float* input = (const float*)d_in[0];   // [B, 16] fp32
    const float* frbw  = (const float*)d_in[1];   // [1024]  fp32
    const float* Cm    = (const float*)d_in[2];   // [32,17] fp32
    float* out = (float*)d_out;                   // [B]     fp32

    int B = in_sizes[0] / NA;
    int blocks = (B + SPB - 1) / SPB;             // 512 blocks for B=65536
    tsk_kernel<<<blocks, TPB>>>(input, frbw, Cm, out, B);
}

// round 9
// speedup vs baseline: 1.1193x; 1.0133x over previous
#include <cuda_runtime.h>
#include <cstdint>

#define NA  16
#define NR  32
#define TPB 128      // 4 warps; warp handles 32 samples, lane = rule
#define SPW 32       // samples per warp
#define SPB 128      // samples per block
#define XROW 20      // floats per staged row (80B: 16B-aligned, one-time write cost)

static __device__ __forceinline__ float ex2(float x) {
    float y;
    asm("ex2.approx.f32 %0, %1;" : "=f"(y) : "f"(x));
    return y;
}

__global__ void __launch_bounds__(TPB, 4)
tsk_kernel(const float* __restrict__ input,
           const float* __restrict__ frbw,
           const float* __restrict__ C,
           float* __restrict__ out, int B)
{
    __shared__ float sx[4][SPW * XROW];     // staged X rows          10.2 KB
    __shared__ float rn[4][NR][33];         // numerator partials     16.9 KB
    __shared__ float rd[4][NR][33];         // denominator partials   16.9 KB

    const float L2E = 1.4426950408889634f;
    const int tid  = threadIdx.x;
    const int w    = tid >> 5;
    const int lane = tid & 31;
    const int ws0  = (blockIdx.x * 4 + w) * SPW;   // first sample of this warp

    // ---- stage this warp's 32 rows (lane l -> row l) ----
    {
        int srow = ws0 + lane;
        if (srow >= B) srow = B - 1;               // clamp tail: duplicates OK
        const float4* gsrc = (const float4*)(input + (size_t)srow * NA);
        float4* dst = (float4*)&sx[w][lane * XROW];
        dst[0] = gsrc[0];
        dst[1] = gsrc[1];
        dst[2] = gsrc[2];
        dst[3] = gsrc[3];
    }

    // ---- per-lane rule coefficients (lane = rule), SCALAR registers ----
    // Faithful to reference: idx = r*A + k; (sigma, center) = FRB_W[idx], FRB_W[idx+1]
    float P[NA], Q[NA], Cc[NA];
    float rc = 0.0f;
    const float* wr = frbw + lane * NA;
    const float* cr = C + lane * (NA + 1);
    #pragma unroll
    for (int k = 0; k < NA; k++) {
        float sig = __ldg(wr + k);
        float cen = __ldg(wr + k + 1);
        float is2 = 1.0f / (sig * sig);
        P[k] = -0.5f * is2 * L2E;
        Q[k] = is2 * cen * L2E;
        Cc[k] = __ldg(cr + k + 1);
        rc += P[k] * cen * cen;       // -0.5*(cen/sig)^2 * log2e
    }
    const float c0 = __ldg(cr);

    __syncwarp();   // staging visible warp-wide (warp-private smem region)

    // ---- main: 16 sample-pairs; 2 interleaved scalar chains per pair ----
    #pragma unroll 1
    for (int p = 0; p < 16; p++) {
        // rows 2p, 2p+1: broadcast LDS.128 x8 (all lanes same address)
        const float4* xa = (const float4*)&sx[w][(2 * p) * XROW];
        const float4* xb = (const float4*)&sx[w][(2 * p + 1) * XROW];
        float4 a0 = xa[0], a1 = xa[1], a2 = xa[2], a3 = xa[3];
        float4 b0 = xb[0], b1 = xb[1], b2 = xb[2], b3 = xb[3];
        float xv0[NA] = {a0.x, a0.y, a0.z, a0.w, a1.x, a1.y, a1.z, a1.w,
                         a2.x, a2.y, a2.z, a2.w, a3.x, a3.y, a3.z, a3.w};
        float xv1[NA] = {b0.x, b0.y, b0.z, b0.w, b1.x, b1.y, b1.z, b1.w,
                         b2.x, b2.y, b2.z, b2.w, b3.x, b3.y, b3.z, b3.w};

        float e0 = rc, ch0 = c0;
        float e1 = rc, ch1 = c0;
        #pragma unroll
        for (int k = 0; k < NA; k++) {
            float t0 = fmaf(P[k], xv0[k], Q[k]);
            float t1 = fmaf(P[k], xv1[k], Q[k]);
            e0  = fmaf(t0, xv0[k], e0);
            e1  = fmaf(t1, xv1[k], e1);
            ch0 = fmaf(Cc[k], xv0[k], ch0);
            ch1 = fmaf(Cc[k], xv1[k], ch1);
        }
        float u0 = ex2(e0);
        float u1 = ex2(e1);
        // fire-and-forget partials (bank-conflict-free: addr = lane*33 + s)
        rn[w][lane][2 * p]     = u0 * ch0;
        rd[w][lane][2 * p]     = u0;
        rn[w][lane][2 * p + 1] = u1 * ch1;
        rd[w][lane][2 * p + 1] = u1;
    }

    __syncwarp();

    // ---- batched reduction: lane = sample, sum over 32 rules ----
    {
        float n0 = 0.f, n1 = 0.f, n2 = 0.f, n3 = 0.f;
        float d0 = 0.f, d1 = 0.f, d2 = 0.f, d3 = 0.f;
        #pragma unroll
        for (int r = 0; r < NR; r += 4) {
            n0 += rn[w][r + 0][lane];
            n1 += rn[w][r + 1][lane];
            n2 += rn[w][r + 2][lane];
            n3 += rn[w][r + 3][lane];
            d0 += rd[w][r + 0][lane];
            d1 += rd[w][r + 1][lane];
            d2 += rd[w][r + 2][lane];
            d3 += rd[w][r + 3][lane];
        }
        float num = (n0 + n1) + (n2 + n3);
        float den = (d0 + d1) + (d2 + d3);
        int s = ws0 + lane;
        if (s < B) out[s] = __fdividef(num, den);
    }
}

extern "C" void kernel_launch(void* const* d_in, const int* in_sizes, int n_in,
                              void* d_out, int out_size)
{
    const float* input = (const float*)d_in[0];   // [B, 16] fp32
    const float* frbw  = (const float*)d_in[1];   // [1024]  fp32
    const float* Cm    = (const float*)d_in[2];   // [32,17] fp32
    float* out = (float*)d_out;                   // [B]     fp32

    int B = in_sizes[0] / NA;
    int blocks = (B + SPB - 1) / SPB;             // 512 blocks for B=65536
    tsk_kernel<<<blocks, TPB>>>(input, frbw, Cm, out, B);
}

// round 10
// speedup vs baseline: 1.1214x; 1.0019x over previous
#include <cuda_runtime.h>
#include <cstdint>

#define NA   16
#define NR   32
#define TPB  128     // 4 warps; lane = rule, warp covers SPWARP samples
#define SPWARP 23    // samples per warp (740 blocks * 4 * 23 = 68080 >= 65536)
#define XS   10      // u64 stride per staged sample row (80B, 16B-aligned)
#define RS   25      // f32 stride per rule row in reduction buffer (odd)

static __device__ __forceinline__ unsigned long long pack2(float lo, float hi) {
    unsigned long long r;
    asm("mov.b64 %0, {%1, %2};" : "=l"(r) : "f"(lo), "f"(hi));
    return r;
}
static __device__ __forceinline__ void unpack2(unsigned long long v, float& lo, float& hi) {
    asm("mov.b64 {%0, %1}, %2;" : "=f"(lo), "=f"(hi) : "l"(v));
}
static __device__ __forceinline__ unsigned long long fma2(
    unsigned long long a, unsigned long long b, unsigned long long c) {
    unsigned long long d;
    asm("fma.rn.f32x2 %0, %1, %2, %3;" : "=l"(d) : "l"(a), "l"(b), "l"(c));
    return d;
}
static __device__ __forceinline__ float ex2(float x) {
    float y;
    asm("ex2.approx.f32 %0, %1;" : "=f"(y) : "f"(x));
    return y;
}

__global__ void __launch_bounds__(TPB, 5)
tsk_kernel(const float* __restrict__ input,
           const float* __restrict__ frbw,
           const float* __restrict__ C,
           float* __restrict__ out, int B)
{
    // Warp-private staging + reduction buffers (no __syncthreads anywhere).
    __shared__ unsigned long long sx[4][SPWARP * XS + 2];   // ~7.4 KB
    __shared__ float rn[4][NR][RS];                         // 12.8 KB
    __shared__ float rd[4][NR][RS];                         // 12.8 KB

    const float L2E = 1.4426950408889634f;
    const int tid  = threadIdx.x;
    const int w    = tid >> 5;
    const int lane = tid & 31;
    const int ws0  = (blockIdx.x * 4 + w) * SPWARP;   // first sample of warp

    // ---- stage this warp's SPWARP rows (lane l -> row l), float4 = packed pairs ----
    if (lane < SPWARP) {
        int srow = ws0 + lane;
        if (srow >= B) srow = B - 1;                  // clamp tail
        const float4* gsrc = (const float4*)(input + (size_t)srow * NA);
        float4* dst = (float4*)&sx[w][lane * XS];     // 80B stride: conflict-free STS.128
        dst[0] = gsrc[0];
        dst[1] = gsrc[1];
        dst[2] = gsrc[2];
        dst[3] = gsrc[3];
    }

    // ---- per-lane rule coefficients (lane = rule), K-PACKED pairs: 24 u64 regs ----
    // Faithful to reference: idx = r*A + k; (sigma, center) = FRB_W[idx], FRB_W[idx+1]
    unsigned long long Pp[8], Qp[8], Cp[8];
    float rce = 0.0f, rco = 0.0f;
    const float* wr = frbw + lane * NA;
    const float* cr = C + lane * (NA + 1);
    #pragma unroll
    for (int j = 0; j < 8; j++) {
        // even k = 2j
        float sig0 = __ldg(wr + 2 * j);
        float cen0 = __ldg(wr + 2 * j + 1);
        float is20 = 1.0f / (sig0 * sig0);
        float p0 = -0.5f * is20 * L2E;
        float q0 = is20 * cen0 * L2E;
        // odd k = 2j+1
        float sig1 = __ldg(wr + 2 * j + 1);
        float cen1 = __ldg(wr + 2 * j + 2);
        float is21 = 1.0f / (sig1 * sig1);
        float p1 = -0.5f * is21 * L2E;
        float q1 = is21 * cen1 * L2E;
        Pp[j] = pack2(p0, p1);
        Qp[j] = pack2(q0, q1);
        Cp[j] = pack2(__ldg(cr + 2 * j + 1), __ldg(cr + 2 * j + 2));
        rce += p0 * cen0 * cen0;
        rco += p1 * cen1 * cen1;
    }
    const unsigned long long RC = pack2(rce, rco);            // exponent const split even/odd
    const unsigned long long C0 = pack2(__ldg(cr), 0.0f);     // bias in even slot

    __syncwarp();   // staging visible warp-wide

    const unsigned long long* xw = sx[w];

    // ---- main: per sample, 4 broadcast LDS.128 + 24 FFMA2 ----
    #pragma unroll 1
    for (int s = 0; s < SPWARP; s++) {
        const ulonglong2* xp = (const ulonglong2*)(xw + s * XS);
        unsigned long long e  = RC;
        unsigned long long ch = C0;
        #pragma unroll
        for (int jj = 0; jj < 4; jj++) {
            ulonglong2 X2 = xp[jj];   // (x[4jj],x[4jj+1] | x[4jj+2],x[4jj+3]) broadcast
            unsigned long long t0 = fma2(Pp[2 * jj],     X2.x, Qp[2 * jj]);
            unsigned long long t1 = fma2(Pp[2 * jj + 1], X2.y, Qp[2 * jj + 1]);
            e  = fma2(t0, X2.x, e);
            ch = fma2(Cp[2 * jj],     X2.x, ch);
            e  = fma2(t1, X2.y, e);
            ch = fma2(Cp[2 * jj + 1], X2.y, ch);
        }
        float ee, eo, che, cho;
        unpack2(e, ee, eo);
        unpack2(ch, che, cho);
        float u = ex2(ee + eo);            // rule firing strength
        float chs = che + cho;
        // fire-and-forget partials (conflict-free: addr = lane*RS + s, RS odd)
        rn[w][lane][s] = u * chs;
        rd[w][lane][s] = u;
    }

    __syncwarp();

    // ---- reduction: lane = sample, sum over 32 rules (conflict-free columns) ----
    if (lane < SPWARP) {
        float n0 = 0.f, n1 = 0.f, n2 = 0.f, n3 = 0.f;
        float d0 = 0.f, d1 = 0.f, d2 = 0.f, d3 = 0.f;
        #pragma unroll
        for (int r = 0; r < NR; r += 4) {
            n0 += rn[w][r + 0][lane];
            n1 += rn[w][r + 1][lane];
            n2 += rn[w][r + 2][lane];
            n3 += rn[w][r + 3][lane];
            d0 += rd[w][r + 0][lane];
            d1 += rd[w][r + 1][lane];
            d2 += rd[w][r + 2][lane];
            d3 += rd[w][r + 3][lane];
        }
        float num = (n0 + n1) + (n2 + n3);
        float den = (d0 + d1) + (d2 + d3);
        int s = ws0 + lane;
        if (s < B) out[s] = __fdividef(num, den);
    }
}

extern "C" void kernel_launch(void* const* d_in, const int* in_sizes, int n_in,
                              void* d_out, int out_size)
{
    const float* input = (const float*)d_in[0];   // [B, 16] fp32
    const float* frbw  = (const float*)d_in[1];   // [1024]  fp32
    const float* Cm    = (const float*)d_in[2];   // [32,17] fp32
    float* out = (float*)d_out;                   // [B]     fp32

    int B = in_sizes[0] / NA;
    int spb = 4 * SPWARP;                          // 92 samples per block
    int blocks = (B + spb - 1) / spb;              // 713 for B=65536 (<740, 1 wave)
    tsk_kernel<<<blocks, TPB>>>(input, frbw, Cm, out, B);
}